// round 4
// baseline (speedup 1.0000x reference)
#include <cuda_runtime.h>
#include <cuda_bf16.h>
#include <math.h>
#include <stdint.h>

// ---------------- problem constants ----------------
#define BB   16
#define CC   256
#define HH   56
#define HWSZ 3136
#define WWIN 7
#define NN   49
#define MM   1024
#define NHD  8
#define HID_ 1024
#define NPTS 50176
#define EPSV 1e-5f

// ---------------- device scratch ----------------
__device__ float g_qkv[(size_t)NPTS * 3 * CC];                 // fp32 (pt, 768)
__device__ float g_o  [(size_t)NPTS * CC];                     // fp32 (pt, 256)
__device__ __nv_bfloat16 s1h[(size_t)NPTS * CC], s1l[(size_t)NPTS * CC];
__device__ __nv_bfloat16 s2h[(size_t)NPTS * CC], s2l[(size_t)NPTS * CC];
__device__ __nv_bfloat16 ghh[(size_t)NPTS * HID_], ghl[(size_t)NPTS * HID_];
__device__ __nv_bfloat16 wqh[3 * CC * CC], wql[3 * CC * CC];
__device__ __nv_bfloat16 wph[CC * CC],     wpl[CC * CC];
__device__ __nv_bfloat16 w1h[HID_ * CC],   w1l[HID_ * CC];
__device__ __nv_bfloat16 w2h[CC * HID_],   w2l[CC * HID_];
__device__ float g_bias[NHD * NN * NN];

// ================= helpers =================
__device__ __forceinline__ void mma16816(float* c, const uint32_t* a, const uint32_t* b) {
    asm volatile(
        "mma.sync.aligned.m16n8k16.row.col.f32.bf16.bf16.f32 "
        "{%0,%1,%2,%3}, {%4,%5,%6,%7}, {%8,%9}, {%0,%1,%2,%3};"
        : "+f"(c[0]), "+f"(c[1]), "+f"(c[2]), "+f"(c[3])
        : "r"(a[0]), "r"(a[1]), "r"(a[2]), "r"(a[3]), "r"(b[0]), "r"(b[1]));
}
__device__ __forceinline__ uint32_t split2(float x, float y, uint32_t& lo2) {
    __nv_bfloat16 hx = __float2bfloat16(x);
    __nv_bfloat16 hy = __float2bfloat16(y);
    float lx = x - __bfloat162float(hx);
    float ly = y - __bfloat162float(hy);
    __nv_bfloat162 h; h.x = hx; h.y = hy;
    __nv_bfloat162 l; l.x = __float2bfloat16(lx); l.y = __float2bfloat16(ly);
    lo2 = *reinterpret_cast<uint32_t*>(&l);
    return *reinterpret_cast<uint32_t*>(&h);
}
__device__ __forceinline__ uint32_t smem_u32(const void* p) {
    uint32_t a;
    asm("{ .reg .u64 t; cvta.to.shared.u64 t, %1; cvt.u32.u64 %0, t; }" : "=r"(a) : "l"(p));
    return a;
}
__device__ __forceinline__ void cp16(uint32_t dst, const void* src) {
    asm volatile("cp.async.cg.shared.global [%0], [%1], 16;" :: "r"(dst), "l"(src));
}
#define CP_COMMIT() asm volatile("cp.async.commit_group;")
#define CP_WAIT(n)  asm volatile("cp.async.wait_group %0;" :: "n"(n))

// ================= bf16 split GEMM, cp.async 3-stage =================
// out[pt][o] = X[pt,:].W[o,:] + bias[o]; modes: 0 fp32, 1 split bf16, 2 gelu+split
#define SPAD   40                       // halves per k-chunk row (80 bytes)
#define TILEH  (128 * SPAD)             // halves per array per stage
#define STAGES 3
#define GSMEM  (4 * STAGES * TILEH * 2) // 122880 bytes

__global__ void __launch_bounds__(256, 1)
k_gemm(const __nv_bfloat16* __restrict__ Wh, const __nv_bfloat16* __restrict__ Wl,
       const float* __restrict__ bias,
       const __nv_bfloat16* __restrict__ Xh, const __nv_bfloat16* __restrict__ Xl,
       float* __restrict__ out, __nv_bfloat16* __restrict__ outh, __nv_bfloat16* __restrict__ outl,
       int IC, int OC, int mode)
{
    extern __shared__ __align__(16) __nv_bfloat16 sm[];
    __nv_bfloat16* Ah = sm;
    __nv_bfloat16* Al = sm + STAGES * TILEH;
    __nv_bfloat16* Bh = sm + 2 * STAGES * TILEH;
    __nv_bfloat16* Bl = sm + 3 * STAGES * TILEH;
    const uint32_t sb = smem_u32(sm);

    const int tid = threadIdx.x, lane = tid & 31, wid = tid >> 5;
    const int p0 = blockIdx.x * 128, o0 = blockIdx.y * 128;
    const int wm = (wid & 1) * 64, wn = (wid >> 1) * 32;
    const int g = lane >> 2, t = lane & 3;

    auto prefetch = [&](int kt, int stage) {
        int c0 = kt * 32;
        uint32_t so = (uint32_t)stage * TILEH * 2;
        #pragma unroll
        for (int i = 0; i < 2; ++i) {
            int idx = tid + i * 256;        // 0..511
            int r = idx >> 2, c16 = idx & 3;
            uint32_t doff = so + (uint32_t)(r * SPAD + c16 * 8) * 2;
            size_t gx = (size_t)(p0 + r) * IC + c0 + c16 * 8;
            size_t gw = (size_t)(o0 + r) * IC + c0 + c16 * 8;
            cp16(sb + doff,                          Xh + gx);
            cp16(sb + STAGES * TILEH * 2 + doff,     Xl + gx);
            cp16(sb + 2 * STAGES * TILEH * 2 + doff, Wh + gw);
            cp16(sb + 3 * STAGES * TILEH * 2 + doff, Wl + gw);
        }
        CP_COMMIT();
    };

    float acc[4][4][4];
    #pragma unroll
    for (int i = 0; i < 4; i++)
        #pragma unroll
        for (int j = 0; j < 4; j++)
            #pragma unroll
            for (int q = 0; q < 4; q++) acc[i][j][q] = 0.f;

    const int KT = IC >> 5;
    prefetch(0, 0);
    prefetch(1, 1);

    for (int kt = 0; kt < KT; ++kt) {
        if (kt + 1 < KT) { CP_WAIT(1); } else { CP_WAIT(0); }
        __syncthreads();
        if (kt + 2 < KT) prefetch(kt + 2, (kt + 2) % 3);

        int stage = kt % 3;
        __nv_bfloat16* ah_s = Ah + stage * TILEH;
        __nv_bfloat16* al_s = Al + stage * TILEH;
        __nv_bfloat16* bh_s = Bh + stage * TILEH;
        __nv_bfloat16* bl_s = Bl + stage * TILEH;

        #pragma unroll
        for (int k0 = 0; k0 < 32; k0 += 16) {
            uint32_t ah[4][4], al[4][4], bh[4][2], bl[4][2];
            int ab = k0 + 2 * t;
            #pragma unroll
            for (int i = 0; i < 4; i++) {
                int base = ab + (wm + i * 16 + g) * SPAD;
                ah[i][0] = *reinterpret_cast<uint32_t*>(&ah_s[base]);
                ah[i][1] = *reinterpret_cast<uint32_t*>(&ah_s[base + 8 * SPAD]);
                ah[i][2] = *reinterpret_cast<uint32_t*>(&ah_s[base + 8]);
                ah[i][3] = *reinterpret_cast<uint32_t*>(&ah_s[base + 8 * SPAD + 8]);
                al[i][0] = *reinterpret_cast<uint32_t*>(&al_s[base]);
                al[i][1] = *reinterpret_cast<uint32_t*>(&al_s[base + 8 * SPAD]);
                al[i][2] = *reinterpret_cast<uint32_t*>(&al_s[base + 8]);
                al[i][3] = *reinterpret_cast<uint32_t*>(&al_s[base + 8 * SPAD + 8]);
            }
            #pragma unroll
            for (int j = 0; j < 4; j++) {
                int base = ab + (wn + j * 8 + g) * SPAD;
                bh[j][0] = *reinterpret_cast<uint32_t*>(&bh_s[base]);
                bh[j][1] = *reinterpret_cast<uint32_t*>(&bh_s[base + 8]);
                bl[j][0] = *reinterpret_cast<uint32_t*>(&bl_s[base]);
                bl[j][1] = *reinterpret_cast<uint32_t*>(&bl_s[base + 8]);
            }
            #pragma unroll
            for (int i = 0; i < 4; i++)
                #pragma unroll
                for (int j = 0; j < 4; j++) mma16816(acc[i][j], ah[i], bh[j]);
            #pragma unroll
            for (int i = 0; i < 4; i++)
                #pragma unroll
                for (int j = 0; j < 4; j++) mma16816(acc[i][j], ah[i], bl[j]);
            #pragma unroll
            for (int i = 0; i < 4; i++)
                #pragma unroll
                for (int j = 0; j < 4; j++) mma16816(acc[i][j], al[i], bh[j]);
        }
    }

    // epilogue
    #pragma unroll
    for (int j = 0; j < 4; j++) {
        int col = o0 + wn + j * 8 + 2 * t;
        float b0 = bias[col], b1 = bias[col + 1];
        #pragma unroll
        for (int i = 0; i < 4; i++) {
            int r0 = p0 + wm + i * 16 + g;
            float v0 = acc[i][j][0] + b0, v1 = acc[i][j][1] + b1;
            float v2 = acc[i][j][2] + b0, v3 = acc[i][j][3] + b1;
            if (mode == 2) {
                v0 = 0.5f * v0 * (1.f + erff(v0 * 0.70710678118654752f));
                v1 = 0.5f * v1 * (1.f + erff(v1 * 0.70710678118654752f));
                v2 = 0.5f * v2 * (1.f + erff(v2 * 0.70710678118654752f));
                v3 = 0.5f * v3 * (1.f + erff(v3 * 0.70710678118654752f));
            }
            if (mode == 0) {
                *reinterpret_cast<float2*>(&out[(size_t)r0 * OC + col])       = make_float2(v0, v1);
                *reinterpret_cast<float2*>(&out[(size_t)(r0 + 8) * OC + col]) = make_float2(v2, v3);
            } else {
                uint32_t l0, l1;
                uint32_t h0 = split2(v0, v1, l0);
                uint32_t h1 = split2(v2, v3, l1);
                *reinterpret_cast<uint32_t*>(&outh[(size_t)r0 * OC + col])       = h0;
                *reinterpret_cast<uint32_t*>(&outl[(size_t)r0 * OC + col])       = l0;
                *reinterpret_cast<uint32_t*>(&outh[(size_t)(r0 + 8) * OC + col]) = h1;
                *reinterpret_cast<uint32_t*>(&outl[(size_t)(r0 + 8) * OC + col]) = l1;
            }
        }
    }
}

// ================= weight split =================
__global__ void k_wsplit(const float* __restrict__ w, __nv_bfloat16* __restrict__ wh,
                         __nv_bfloat16* __restrict__ wl, int n) {
    int i = blockIdx.x * blockDim.x + threadIdx.x;
    if (i >= n) return;
    float v = w[i];
    __nv_bfloat16 h = __float2bfloat16(v);
    wh[i] = h;
    wl[i] = __float2bfloat16(v - __bfloat162float(h));
}

// ================= relative-position bias =================
__global__ void k_bias(const float* __restrict__ table, float* __restrict__ bias) {
    int i = blockIdx.x * blockDim.x + threadIdx.x;
    if (i >= NHD * NN * NN) return;
    int h = i / (NN * NN);
    int rem = i % (NN * NN);
    int n = rem / NN, k = rem % NN;
    int dr = n / WWIN - k / WWIN + (WWIN - 1);
    int dc = n % WWIN - k % WWIN + (WWIN - 1);
    bias[i] = table[(dr * (2 * WWIN - 1) + dc) * NHD + h];
}

// ================= channel LayerNorm -> split bf16 (pt, C) =================
template <bool BLOCKED>
__global__ void k_ln(const float* __restrict__ x, const float* __restrict__ w,
                     const float* __restrict__ b,
                     __nv_bfloat16* __restrict__ oh, __nv_bfloat16* __restrict__ ol) {
    int blk = blockIdx.x;
    int w0  = (blk & 1) * 28;
    int bh  = blk >> 1;
    int h   = bh % HH;
    int bb  = bh / HH;
    int tx = threadIdx.x, ty = threadIdx.y;
    int wpos = w0 + tx;

    const float* xb = x + (size_t)bb * CC * HWSZ + h * HH + wpos;

    float s = 0.f, s2 = 0.f;
    #pragma unroll
    for (int c = ty; c < CC; c += 8) {
        float v = xb[(size_t)c * HWSZ];
        s += v; s2 += v * v;
    }
    __shared__ float sh_s[8][28], sh_s2[8][28];
    __shared__ float sh_mu[28], sh_rs[28];
    sh_s[ty][tx] = s; sh_s2[ty][tx] = s2;
    __syncthreads();
    if (ty == 0) {
        float ts = 0.f, ts2 = 0.f;
        #pragma unroll
        for (int j = 0; j < 8; j++) { ts += sh_s[j][tx]; ts2 += sh_s2[j][tx]; }
        float mu  = ts * (1.f / CC);
        float var = ts2 * (1.f / CC) - mu * mu;
        sh_mu[tx] = mu; sh_rs[tx] = rsqrtf(var + EPSV);
    }
    __syncthreads();
    float mu = sh_mu[tx], rs = sh_rs[tx];

    size_t pt;
    if (BLOCKED) {
        int m = bb * 64 + (h / WWIN) * 8 + (wpos / WWIN);
        int n = (h % WWIN) * WWIN + (wpos % WWIN);
        pt = (size_t)m * NN + n;
    } else {
        pt = (size_t)bb * HWSZ + h * HH + wpos;
    }
    __nv_bfloat16* ohb = oh + pt * CC;
    __nv_bfloat16* olb = ol + pt * CC;
    #pragma unroll
    for (int c = ty; c < CC; c += 8) {
        float v = (xb[(size_t)c * HWSZ] - mu) * rs * w[c] + b[c];
        __nv_bfloat16 hv = __float2bfloat16(v);
        ohb[c] = hv;
        olb[c] = __float2bfloat16(v - __bfloat162float(hv));
    }
}

// ================= attention core (register-blocked) =================
__global__ void __launch_bounds__(256, 2)
k_attn(const float* __restrict__ qkv, const float* __restrict__ bias,
       __nv_bfloat16* __restrict__ outh, __nv_bfloat16* __restrict__ outl) {
    int m = blockIdx.x >> 3;
    int h = blockIdx.x & 7;

    __shared__ float sqd[32 * 52];       // q^T: [d][n], q pre-scaled
    __shared__ float skd[32 * 52];       // k^T: [d][kk]
    __shared__ float sv [NN * 36];       // v  : [kk][d]
    __shared__ float at_nk[NN * 52];     // scores [n][kk]
    __shared__ float at_kn[NN * 52];     // probs^T [kk][n]

    const int tid = threadIdx.x;
    const float scale = 0.17677669529663687f;
    const float* baseq = qkv + (size_t)(m * NN) * (3 * CC) + h * 32;

    for (int i = tid; i < NN * 8; i += 256) {
        int n = i >> 3, d4 = (i & 7) << 2;
        const float* rp = baseq + (size_t)n * (3 * CC);
        float4 q4 = *reinterpret_cast<const float4*>(rp + d4);
        float4 k4 = *reinterpret_cast<const float4*>(rp + CC + d4);
        float4 v4 = *reinterpret_cast<const float4*>(rp + 2 * CC + d4);
        sqd[(d4 + 0) * 52 + n] = q4.x * scale;
        sqd[(d4 + 1) * 52 + n] = q4.y * scale;
        sqd[(d4 + 2) * 52 + n] = q4.z * scale;
        sqd[(d4 + 3) * 52 + n] = q4.w * scale;
        skd[(d4 + 0) * 52 + n] = k4.x;
        skd[(d4 + 1) * 52 + n] = k4.y;
        skd[(d4 + 2) * 52 + n] = k4.z;
        skd[(d4 + 3) * 52 + n] = k4.w;
        *reinterpret_cast<float4*>(&sv[n * 36 + d4]) = v4;
    }
    __syncthreads();

    // scores: 13x13 threads, 4x4 tiles
    if (tid < 169) {
        int i = tid % 13, j = tid / 13;
        int n0 = 4 * i, k0 = 4 * j;
        float acc[4][4];
        #pragma unroll
        for (int a = 0; a < 4; a++)
            #pragma unroll
            for (int bq = 0; bq < 4; bq++) acc[a][bq] = 0.f;
        #pragma unroll 8
        for (int d = 0; d < 32; d++) {
            float4 qv = *reinterpret_cast<const float4*>(&sqd[d * 52 + n0]);
            float4 kv = *reinterpret_cast<const float4*>(&skd[d * 52 + k0]);
            acc[0][0] += qv.x * kv.x; acc[0][1] += qv.x * kv.y; acc[0][2] += qv.x * kv.z; acc[0][3] += qv.x * kv.w;
            acc[1][0] += qv.y * kv.x; acc[1][1] += qv.y * kv.y; acc[1][2] += qv.y * kv.z; acc[1][3] += qv.y * kv.w;
            acc[2][0] += qv.z * kv.x; acc[2][1] += qv.z * kv.y; acc[2][2] += qv.z * kv.z; acc[2][3] += qv.z * kv.w;
            acc[3][0] += qv.w * kv.x; acc[3][1] += qv.w * kv.y; acc[3][2] += qv.w * kv.z; acc[3][3] += qv.w * kv.w;
        }
        const float* bh = bias + h * NN * NN;
        #pragma unroll
        for (int a = 0; a < 4; a++) {
            int n = n0 + a;
            if (n < NN) {
                #pragma unroll
                for (int bq = 0; bq < 4; bq++) {
                    int kk = k0 + bq;
                    if (kk < NN) at_nk[n * 52 + kk] = acc[a][bq] + bh[n * NN + kk];
                }
            }
        }
    }
    __syncthreads();

    // softmax rows + transposed prob write
    int warp = tid >> 5, lane = tid & 31;
    for (int n = warp; n < NN; n += 8) {
        float v0 = at_nk[n * 52 + lane];
        float v1 = (lane + 32 < NN) ? at_nk[n * 52 + lane + 32] : -INFINITY;
        float mx = fmaxf(v0, v1);
        #pragma unroll
        for (int o = 16; o; o >>= 1) mx = fmaxf(mx, __shfl_xor_sync(0xffffffffu, mx, o));
        float e0 = __expf(v0 - mx);
        float e1 = (lane + 32 < NN) ? __expf(v1 - mx) : 0.f;
        float s = e0 + e1;
        #pragma unroll
        for (int o = 16; o; o >>= 1) s += __shfl_xor_sync(0xffffffffu, s, o);
        float inv = 1.f / s;
        at_kn[lane * 52 + n] = e0 * inv;
        if (lane + 32 < NN) at_kn[(lane + 32) * 52 + n] = e1 * inv;
    }
    __syncthreads();

    // AV: 13x8 threads, 4x4 tiles (n x d), split-bf16 output
    if (tid < 104) {
        int i = tid % 13, j = tid / 13;
        int n0 = 4 * i, d0 = 4 * j;
        float acc[4][4];
        #pragma unroll
        for (int a = 0; a < 4; a++)
            #pragma unroll
            for (int bq = 0; bq < 4; bq++) acc[a][bq] = 0.f;
        #pragma unroll 7
        for (int kk = 0; kk < NN; kk++) {
            float4 av = *reinterpret_cast<const float4*>(&at_kn[kk * 52 + n0]);
            float4 vv = *reinterpret_cast<const float4*>(&sv[kk * 36 + d0]);
            acc[0][0] += av.x * vv.x; acc[0][1] += av.x * vv.y; acc[0][2] += av.x * vv.z; acc[0][3] += av.x * vv.w;
            acc[1][0] += av.y * vv.x; acc[1][1] += av.y * vv.y; acc[1][2] += av.y * vv.z; acc[1][3] += av.y * vv.w;
            acc[2][0] += av.z * vv.x; acc[2][1] += av.z * vv.y; acc[2][2] += av.z * vv.z; acc[2][3] += av.z * vv.w;
            acc[3][0] += av.w * vv.x; acc[3][1] += av.w * vv.y; acc[3][2] += av.w * vv.z; acc[3][3] += av.w * vv.w;
        }
        #pragma unroll
        for (int a = 0; a < 4; a++) {
            int n = n0 + a;
            if (n < NN) {
                size_t o = (size_t)(m * NN + n) * CC + h * 32 + d0;
                uint32_t l0, l1;
                uint32_t h0 = split2(acc[a][0], acc[a][1], l0);
                uint32_t h1 = split2(acc[a][2], acc[a][3], l1);
                *reinterpret_cast<uint2*>(&outh[o]) = make_uint2(h0, h1);
                *reinterpret_cast<uint2*>(&outl[o]) = make_uint2(l0, l1);
            }
        }
    }
}

// ================= residuals =================
__global__ void k_resid(const float* __restrict__ x, const float* __restrict__ y,
                        float* __restrict__ out) {
    int i = blockIdx.x * blockDim.x + threadIdx.x;
    if (i >= BB * CC * HWSZ) return;
    int w = i % HH; int t = i / HH;
    int h = t % HH;  t /= HH;
    int c = t % CC;  int b = t / CC;
    int m = b * 64 + (h / WWIN) * 8 + (w / WWIN);
    int n = (h % WWIN) * WWIN + (w % WWIN);
    out[i] = x[i] + y[(size_t)(m * NN + n) * CC + c];
}
__global__ void k_resid2(float* __restrict__ out, const float* __restrict__ z) {
    int i = blockIdx.x * blockDim.x + threadIdx.x;
    if (i >= BB * CC * HWSZ) return;
    int hw = i % HWSZ;
    int c  = (i / HWSZ) % CC;
    int b  = i / (HWSZ * CC);
    out[i] += z[((size_t)b * HWSZ + hw) * CC + c];
}

// ================= host launcher =================
extern "C" void kernel_launch(void* const* d_in, const int* in_sizes, int n_in,
                              void* d_out, int out_size) {
    const float* x      = (const float*)d_in[0];
    const float* ln1_w  = (const float*)d_in[1];
    const float* ln1_b  = (const float*)d_in[2];
    const float* ln2_w  = (const float*)d_in[3];
    const float* ln2_b  = (const float*)d_in[4];
    const float* qkv_w  = (const float*)d_in[5];
    const float* qkv_b  = (const float*)d_in[6];
    const float* proj_w = (const float*)d_in[7];
    const float* proj_b = (const float*)d_in[8];
    const float* table  = (const float*)d_in[9];
    const float* fc1_w  = (const float*)d_in[10];
    const float* fc1_b  = (const float*)d_in[11];
    const float* fc2_w  = (const float*)d_in[12];
    const float* fc2_b  = (const float*)d_in[13];
    float* out = (float*)d_out;

    float *p_qkv, *p_o, *p_bias;
    __nv_bfloat16 *p_s1h, *p_s1l, *p_s2h, *p_s2l, *p_ghh, *p_ghl;
    __nv_bfloat16 *p_wqh, *p_wql, *p_wph, *p_wpl, *p_w1h, *p_w1l, *p_w2h, *p_w2l;
    cudaGetSymbolAddress((void**)&p_qkv, g_qkv);
    cudaGetSymbolAddress((void**)&p_o,   g_o);
    cudaGetSymbolAddress((void**)&p_bias,g_bias);
    cudaGetSymbolAddress((void**)&p_s1h, s1h); cudaGetSymbolAddress((void**)&p_s1l, s1l);
    cudaGetSymbolAddress((void**)&p_s2h, s2h); cudaGetSymbolAddress((void**)&p_s2l, s2l);
    cudaGetSymbolAddress((void**)&p_ghh, ghh); cudaGetSymbolAddress((void**)&p_ghl, ghl);
    cudaGetSymbolAddress((void**)&p_wqh, wqh); cudaGetSymbolAddress((void**)&p_wql, wql);
    cudaGetSymbolAddress((void**)&p_wph, wph); cudaGetSymbolAddress((void**)&p_wpl, wpl);
    cudaGetSymbolAddress((void**)&p_w1h, w1h); cudaGetSymbolAddress((void**)&p_w1l, w1l);
    cudaGetSymbolAddress((void**)&p_w2h, w2h); cudaGetSymbolAddress((void**)&p_w2l, w2l);

    cudaFuncSetAttribute(k_gemm, cudaFuncAttributeMaxDynamicSharedMemorySize, GSMEM);

    k_bias<<<(NHD * NN * NN + 255) / 256, 256>>>(table, p_bias);
    k_wsplit<<<(3 * CC * CC + 255) / 256, 256>>>(qkv_w, p_wqh, p_wql, 3 * CC * CC);
    k_wsplit<<<(CC * CC + 255) / 256, 256>>>(proj_w, p_wph, p_wpl, CC * CC);
    k_wsplit<<<(HID_ * CC + 255) / 256, 256>>>(fc1_w, p_w1h, p_w1l, HID_ * CC);
    k_wsplit<<<(CC * HID_ + 255) / 256, 256>>>(fc2_w, p_w2h, p_w2l, CC * HID_);

    k_ln<true><<<BB * HH * 2, dim3(28, 8)>>>(x, ln1_w, ln1_b, p_s1h, p_s1l);

    // attention pass 1
    k_gemm<<<dim3(NPTS / 128, 6), 256, GSMEM>>>(p_wqh, p_wql, qkv_b, p_s1h, p_s1l,
                                                p_qkv, nullptr, nullptr, CC, 3 * CC, 0);
    k_attn<<<MM * NHD, 256>>>(p_qkv, p_bias, p_s2h, p_s2l);
    k_gemm<<<dim3(NPTS / 128, 2), 256, GSMEM>>>(p_wph, p_wpl, proj_b, p_s2h, p_s2l,
                                                nullptr, p_s1h, p_s1l, CC, CC, 1);

    // attention pass 2
    k_gemm<<<dim3(NPTS / 128, 6), 256, GSMEM>>>(p_wqh, p_wql, qkv_b, p_s1h, p_s1l,
                                                p_qkv, nullptr, nullptr, CC, 3 * CC, 0);
    k_attn<<<MM * NHD, 256>>>(p_qkv, p_bias, p_s2h, p_s2l);
    k_gemm<<<dim3(NPTS / 128, 2), 256, GSMEM>>>(p_wph, p_wpl, proj_b, p_s2h, p_s2l,
                                                p_o, nullptr, nullptr, CC, CC, 0);

    // residual + unblock
    k_resid<<<(BB * CC * HWSZ + 255) / 256, 256>>>(x, p_o, out);

    // LN2 -> split (pt, C)
    k_ln<false><<<BB * HH * 2, dim3(28, 8)>>>(out, ln2_w, ln2_b, p_s1h, p_s1l);

    // MLP
    k_gemm<<<dim3(NPTS / 128, HID_ / 128), 256, GSMEM>>>(p_w1h, p_w1l, fc1_b, p_s1h, p_s1l,
                                                         nullptr, p_ghh, p_ghl, CC, HID_, 2);
    k_gemm<<<dim3(NPTS / 128, CC / 128), 256, GSMEM>>>(p_w2h, p_w2l, fc2_b, p_ghh, p_ghl,
                                                       p_o, nullptr, nullptr, HID_, CC, 0);
    k_resid2<<<(BB * CC * HWSZ + 255) / 256, 256>>>(out, p_o);
}

// round 5
// speedup vs baseline: 1.0342x; 1.0342x over previous
#include <cuda_runtime.h>
#include <cuda_bf16.h>
#include <math.h>
#include <stdint.h>

// ---------------- problem constants ----------------
#define BB   16
#define CC   256
#define HH   56
#define HWSZ 3136
#define WWIN 7
#define NN   49
#define MM   1024
#define NHD  8
#define HID_ 1024
#define NPTS 50176
#define EPSV 1e-5f

// ---------------- device scratch ----------------
__device__ float g_qkv[(size_t)NPTS * 3 * CC];
__device__ float g_o  [(size_t)NPTS * CC];
__device__ __nv_bfloat16 s1h[(size_t)NPTS * CC], s1l[(size_t)NPTS * CC];
__device__ __nv_bfloat16 s2h[(size_t)NPTS * CC], s2l[(size_t)NPTS * CC];
__device__ __nv_bfloat16 ghh[(size_t)NPTS * HID_], ghl[(size_t)NPTS * HID_];
__device__ __nv_bfloat16 wqh[3 * CC * CC], wql[3 * CC * CC];
__device__ __nv_bfloat16 wph[CC * CC],     wpl[CC * CC];
__device__ __nv_bfloat16 w1h[HID_ * CC],   w1l[HID_ * CC];
__device__ __nv_bfloat16 w2h[CC * HID_],   w2l[CC * HID_];
__device__ float g_bias[NHD * NN * NN];

// ================= helpers =================
__device__ __forceinline__ void mma16816(float* c, const uint32_t* a, const uint32_t* b) {
    asm volatile(
        "mma.sync.aligned.m16n8k16.row.col.f32.bf16.bf16.f32 "
        "{%0,%1,%2,%3}, {%4,%5,%6,%7}, {%8,%9}, {%0,%1,%2,%3};"
        : "+f"(c[0]), "+f"(c[1]), "+f"(c[2]), "+f"(c[3])
        : "r"(a[0]), "r"(a[1]), "r"(a[2]), "r"(a[3]), "r"(b[0]), "r"(b[1]));
}
__device__ __forceinline__ uint32_t split2(float x, float y, uint32_t& lo2) {
    __nv_bfloat16 hx = __float2bfloat16(x);
    __nv_bfloat16 hy = __float2bfloat16(y);
    float lx = x - __bfloat162float(hx);
    float ly = y - __bfloat162float(hy);
    __nv_bfloat162 h; h.x = hx; h.y = hy;
    __nv_bfloat162 l; l.x = __float2bfloat16(lx); l.y = __float2bfloat16(ly);
    lo2 = *reinterpret_cast<uint32_t*>(&l);
    return *reinterpret_cast<uint32_t*>(&h);
}

// ================= bf16 split GEMM (reg-staged double buffer) =================
// out[pt][o] = X[pt,:].W[o,:] + bias[o]; modes: 0 fp32, 1 split bf16, 2 gelu+split
#define SPAD  40
#define TILEH (128 * SPAD)
#define GSMEM (8 * TILEH * 2)    // 81920 bytes

__global__ void __launch_bounds__(256, 1)
k_gemm(const __nv_bfloat16* __restrict__ Wh, const __nv_bfloat16* __restrict__ Wl,
       const float* __restrict__ bias,
       const __nv_bfloat16* __restrict__ Xh, const __nv_bfloat16* __restrict__ Xl,
       float* __restrict__ out, __nv_bfloat16* __restrict__ outh, __nv_bfloat16* __restrict__ outl,
       int IC, int OC, int mode)
{
    extern __shared__ __align__(16) __nv_bfloat16 sm[];
    __nv_bfloat16* Ah = sm;
    __nv_bfloat16* Al = sm + 2 * TILEH;
    __nv_bfloat16* Bh = sm + 4 * TILEH;
    __nv_bfloat16* Bl = sm + 6 * TILEH;

    const int tid = threadIdx.x, lane = tid & 31, wid = tid >> 5;
    const int p0 = blockIdx.x * 128, o0 = blockIdx.y * 128;
    const int wm = (wid & 1) * 64, wn = (wid >> 1) * 32;
    const int g = lane >> 2, t = lane & 3;
    const int lrow = tid >> 2, lc8 = (tid & 3) << 3;   // 64 rows x 4 16B-chunks per iter

    float acc[4][4][4];
    #pragma unroll
    for (int i = 0; i < 4; i++)
        #pragma unroll
        for (int j = 0; j < 4; j++)
            #pragma unroll
            for (int q = 0; q < 4; q++) acc[i][j][q] = 0.f;

    uint4 rxh[2], rxl[2], rwh[2], rwl[2];

    auto fetch = [&](int kt) {
        int c0 = kt * 32;
        #pragma unroll
        for (int i = 0; i < 2; ++i) {
            int r = lrow + i * 64;
            size_t gx = (size_t)(p0 + r) * IC + c0 + lc8;
            size_t gw = (size_t)(o0 + r) * IC + c0 + lc8;
            rxh[i] = *reinterpret_cast<const uint4*>(Xh + gx);
            rxl[i] = *reinterpret_cast<const uint4*>(Xl + gx);
            rwh[i] = *reinterpret_cast<const uint4*>(Wh + gw);
            rwl[i] = *reinterpret_cast<const uint4*>(Wl + gw);
        }
    };
    auto stash = [&](int buf) {
        #pragma unroll
        for (int i = 0; i < 2; ++i) {
            int r = lrow + i * 64;
            int ha = buf * TILEH + r * SPAD + lc8;
            *reinterpret_cast<uint4*>(&Ah[ha]) = rxh[i];
            *reinterpret_cast<uint4*>(&Al[ha]) = rxl[i];
            *reinterpret_cast<uint4*>(&Bh[ha]) = rwh[i];
            *reinterpret_cast<uint4*>(&Bl[ha]) = rwl[i];
        }
    };
    auto compute = [&](int buf) {
        #pragma unroll
        for (int k0 = 0; k0 < 32; k0 += 16) {
            uint32_t ah[4][4], al[4][4], bh[4][2], bl[4][2];
            int ab = buf * TILEH + k0 + 2 * t;
            #pragma unroll
            for (int i = 0; i < 4; i++) {
                int base = ab + (wm + i * 16 + g) * SPAD;
                ah[i][0] = *reinterpret_cast<uint32_t*>(&Ah[base]);
                ah[i][1] = *reinterpret_cast<uint32_t*>(&Ah[base + 8 * SPAD]);
                ah[i][2] = *reinterpret_cast<uint32_t*>(&Ah[base + 8]);
                ah[i][3] = *reinterpret_cast<uint32_t*>(&Ah[base + 8 * SPAD + 8]);
                al[i][0] = *reinterpret_cast<uint32_t*>(&Al[base]);
                al[i][1] = *reinterpret_cast<uint32_t*>(&Al[base + 8 * SPAD]);
                al[i][2] = *reinterpret_cast<uint32_t*>(&Al[base + 8]);
                al[i][3] = *reinterpret_cast<uint32_t*>(&Al[base + 8 * SPAD + 8]);
            }
            #pragma unroll
            for (int j = 0; j < 4; j++) {
                int base = ab + (wn + j * 8 + g) * SPAD;
                bh[j][0] = *reinterpret_cast<uint32_t*>(&Bh[base]);
                bh[j][1] = *reinterpret_cast<uint32_t*>(&Bh[base + 8]);
                bl[j][0] = *reinterpret_cast<uint32_t*>(&Bl[base]);
                bl[j][1] = *reinterpret_cast<uint32_t*>(&Bl[base + 8]);
            }
            #pragma unroll
            for (int i = 0; i < 4; i++)
                #pragma unroll
                for (int j = 0; j < 4; j++) mma16816(acc[i][j], ah[i], bh[j]);
            #pragma unroll
            for (int i = 0; i < 4; i++)
                #pragma unroll
                for (int j = 0; j < 4; j++) mma16816(acc[i][j], ah[i], bl[j]);
            #pragma unroll
            for (int i = 0; i < 4; i++)
                #pragma unroll
                for (int j = 0; j < 4; j++) mma16816(acc[i][j], al[i], bh[j]);
        }
    };

    fetch(0); stash(0);
    __syncthreads();
    const int KT = IC >> 5;
    for (int kt = 0; kt < KT; ++kt) {
        int buf = kt & 1;
        if (kt + 1 < KT) fetch(kt + 1);
        compute(buf);
        if (kt + 1 < KT) stash(buf ^ 1);
        __syncthreads();
    }

    // epilogue
    #pragma unroll
    for (int j = 0; j < 4; j++) {
        int col = o0 + wn + j * 8 + 2 * t;
        float b0 = bias[col], b1 = bias[col + 1];
        #pragma unroll
        for (int i = 0; i < 4; i++) {
            int r0 = p0 + wm + i * 16 + g;
            float v0 = acc[i][j][0] + b0, v1 = acc[i][j][1] + b1;
            float v2 = acc[i][j][2] + b0, v3 = acc[i][j][3] + b1;
            if (mode == 2) {
                v0 = 0.5f * v0 * (1.f + erff(v0 * 0.70710678118654752f));
                v1 = 0.5f * v1 * (1.f + erff(v1 * 0.70710678118654752f));
                v2 = 0.5f * v2 * (1.f + erff(v2 * 0.70710678118654752f));
                v3 = 0.5f * v3 * (1.f + erff(v3 * 0.70710678118654752f));
            }
            if (mode == 0) {
                *reinterpret_cast<float2*>(&out[(size_t)r0 * OC + col])       = make_float2(v0, v1);
                *reinterpret_cast<float2*>(&out[(size_t)(r0 + 8) * OC + col]) = make_float2(v2, v3);
            } else {
                uint32_t l0, l1;
                uint32_t h0 = split2(v0, v1, l0);
                uint32_t h1 = split2(v2, v3, l1);
                *reinterpret_cast<uint32_t*>(&outh[(size_t)r0 * OC + col])       = h0;
                *reinterpret_cast<uint32_t*>(&outl[(size_t)r0 * OC + col])       = l0;
                *reinterpret_cast<uint32_t*>(&outh[(size_t)(r0 + 8) * OC + col]) = h1;
                *reinterpret_cast<uint32_t*>(&outl[(size_t)(r0 + 8) * OC + col]) = l1;
            }
        }
    }
}

// ================= weight split =================
__global__ void k_wsplit(const float* __restrict__ w, __nv_bfloat16* __restrict__ wh,
                         __nv_bfloat16* __restrict__ wl, int n) {
    int i = blockIdx.x * blockDim.x + threadIdx.x;
    if (i >= n) return;
    float v = w[i];
    __nv_bfloat16 h = __float2bfloat16(v);
    wh[i] = h;
    wl[i] = __float2bfloat16(v - __bfloat162float(h));
}

// ================= relative-position bias =================
__global__ void k_bias(const float* __restrict__ table, float* __restrict__ bias) {
    int i = blockIdx.x * blockDim.x + threadIdx.x;
    if (i >= NHD * NN * NN) return;
    int h = i / (NN * NN);
    int rem = i % (NN * NN);
    int n = rem / NN, k = rem % NN;
    int dr = n / WWIN - k / WWIN + (WWIN - 1);
    int dc = n % WWIN - k % WWIN + (WWIN - 1);
    bias[i] = table[(dr * (2 * WWIN - 1) + dc) * NHD + h];
}

// ================= channel LayerNorm -> split bf16 (pt, C) =================
template <bool BLOCKED>
__global__ void k_ln(const float* __restrict__ x, const float* __restrict__ w,
                     const float* __restrict__ b,
                     __nv_bfloat16* __restrict__ oh, __nv_bfloat16* __restrict__ ol) {
    int blk = blockIdx.x;
    int w0  = (blk & 1) * 28;
    int bh  = blk >> 1;
    int h   = bh % HH;
    int bb  = bh / HH;
    int tx = threadIdx.x, ty = threadIdx.y;
    int wpos = w0 + tx;

    const float* xb = x + (size_t)bb * CC * HWSZ + h * HH + wpos;

    float s = 0.f, s2 = 0.f;
    #pragma unroll
    for (int c = ty; c < CC; c += 8) {
        float v = xb[(size_t)c * HWSZ];
        s += v; s2 += v * v;
    }
    __shared__ float sh_s[8][28], sh_s2[8][28];
    __shared__ float sh_mu[28], sh_rs[28];
    sh_s[ty][tx] = s; sh_s2[ty][tx] = s2;
    __syncthreads();
    if (ty == 0) {
        float ts = 0.f, ts2 = 0.f;
        #pragma unroll
        for (int j = 0; j < 8; j++) { ts += sh_s[j][tx]; ts2 += sh_s2[j][tx]; }
        float mu  = ts * (1.f / CC);
        float var = ts2 * (1.f / CC) - mu * mu;
        sh_mu[tx] = mu; sh_rs[tx] = rsqrtf(var + EPSV);
    }
    __syncthreads();
    float mu = sh_mu[tx], rs = sh_rs[tx];

    size_t pt;
    if (BLOCKED) {
        int m = bb * 64 + (h / WWIN) * 8 + (wpos / WWIN);
        int n = (h % WWIN) * WWIN + (wpos % WWIN);
        pt = (size_t)m * NN + n;
    } else {
        pt = (size_t)bb * HWSZ + h * HH + wpos;
    }
    __nv_bfloat16* ohb = oh + pt * CC;
    __nv_bfloat16* olb = ol + pt * CC;
    #pragma unroll
    for (int c = ty; c < CC; c += 8) {
        float v = (xb[(size_t)c * HWSZ] - mu) * rs * w[c] + b[c];
        __nv_bfloat16 hv = __float2bfloat16(v);
        ohb[c] = hv;
        olb[c] = __float2bfloat16(v - __bfloat162float(hv));
    }
}

// ================= attention core (register-blocked) =================
__global__ void __launch_bounds__(256, 2)
k_attn(const float* __restrict__ qkv, const float* __restrict__ bias,
       __nv_bfloat16* __restrict__ outh, __nv_bfloat16* __restrict__ outl) {
    int m = blockIdx.x >> 3;
    int h = blockIdx.x & 7;

    __shared__ float sqd[32 * 52];
    __shared__ float skd[32 * 52];
    __shared__ float sv [NN * 36];
    __shared__ float at_nk[NN * 52];
    __shared__ float at_kn[NN * 52];

    const int tid = threadIdx.x;
    const float scale = 0.17677669529663687f;
    const float* baseq = qkv + (size_t)(m * NN) * (3 * CC) + h * 32;

    for (int i = tid; i < NN * 8; i += 256) {
        int n = i >> 3, d4 = (i & 7) << 2;
        const float* rp = baseq + (size_t)n * (3 * CC);
        float4 q4 = *reinterpret_cast<const float4*>(rp + d4);
        float4 k4 = *reinterpret_cast<const float4*>(rp + CC + d4);
        float4 v4 = *reinterpret_cast<const float4*>(rp + 2 * CC + d4);
        sqd[(d4 + 0) * 52 + n] = q4.x * scale;
        sqd[(d4 + 1) * 52 + n] = q4.y * scale;
        sqd[(d4 + 2) * 52 + n] = q4.z * scale;
        sqd[(d4 + 3) * 52 + n] = q4.w * scale;
        skd[(d4 + 0) * 52 + n] = k4.x;
        skd[(d4 + 1) * 52 + n] = k4.y;
        skd[(d4 + 2) * 52 + n] = k4.z;
        skd[(d4 + 3) * 52 + n] = k4.w;
        *reinterpret_cast<float4*>(&sv[n * 36 + d4]) = v4;
    }
    __syncthreads();

    if (tid < 169) {
        int i = tid % 13, j = tid / 13;
        int n0 = 4 * i, k0 = 4 * j;
        float acc[4][4];
        #pragma unroll
        for (int a = 0; a < 4; a++)
            #pragma unroll
            for (int bq = 0; bq < 4; bq++) acc[a][bq] = 0.f;
        #pragma unroll 8
        for (int d = 0; d < 32; d++) {
            float4 qv = *reinterpret_cast<const float4*>(&sqd[d * 52 + n0]);
            float4 kv = *reinterpret_cast<const float4*>(&skd[d * 52 + k0]);
            acc[0][0] += qv.x * kv.x; acc[0][1] += qv.x * kv.y; acc[0][2] += qv.x * kv.z; acc[0][3] += qv.x * kv.w;
            acc[1][0] += qv.y * kv.x; acc[1][1] += qv.y * kv.y; acc[1][2] += qv.y * kv.z; acc[1][3] += qv.y * kv.w;
            acc[2][0] += qv.z * kv.x; acc[2][1] += qv.z * kv.y; acc[2][2] += qv.z * kv.z; acc[2][3] += qv.z * kv.w;
            acc[3][0] += qv.w * kv.x; acc[3][1] += qv.w * kv.y; acc[3][2] += qv.w * kv.z; acc[3][3] += qv.w * kv.w;
        }
        const float* bh = bias + h * NN * NN;
        #pragma unroll
        for (int a = 0; a < 4; a++) {
            int n = n0 + a;
            if (n < NN) {
                #pragma unroll
                for (int bq = 0; bq < 4; bq++) {
                    int kk = k0 + bq;
                    if (kk < NN) at_nk[n * 52 + kk] = acc[a][bq] + bh[n * NN + kk];
                }
            }
        }
    }
    __syncthreads();

    int warp = tid >> 5, lane = tid & 31;
    for (int n = warp; n < NN; n += 8) {
        float v0 = at_nk[n * 52 + lane];
        float v1 = (lane + 32 < NN) ? at_nk[n * 52 + lane + 32] : -INFINITY;
        float mx = fmaxf(v0, v1);
        #pragma unroll
        for (int o = 16; o; o >>= 1) mx = fmaxf(mx, __shfl_xor_sync(0xffffffffu, mx, o));
        float e0 = __expf(v0 - mx);
        float e1 = (lane + 32 < NN) ? __expf(v1 - mx) : 0.f;
        float s = e0 + e1;
        #pragma unroll
        for (int o = 16; o; o >>= 1) s += __shfl_xor_sync(0xffffffffu, s, o);
        float inv = 1.f / s;
        at_kn[lane * 52 + n] = e0 * inv;
        if (lane + 32 < NN) at_kn[(lane + 32) * 52 + n] = e1 * inv;
    }
    __syncthreads();

    if (tid < 104) {
        int i = tid % 13, j = tid / 13;
        int n0 = 4 * i, d0 = 4 * j;
        float acc[4][4];
        #pragma unroll
        for (int a = 0; a < 4; a++)
            #pragma unroll
            for (int bq = 0; bq < 4; bq++) acc[a][bq] = 0.f;
        #pragma unroll 7
        for (int kk = 0; kk < NN; kk++) {
            float4 av = *reinterpret_cast<const float4*>(&at_kn[kk * 52 + n0]);
            float4 vv = *reinterpret_cast<const float4*>(&sv[kk * 36 + d0]);
            acc[0][0] += av.x * vv.x; acc[0][1] += av.x * vv.y; acc[0][2] += av.x * vv.z; acc[0][3] += av.x * vv.w;
            acc[1][0] += av.y * vv.x; acc[1][1] += av.y * vv.y; acc[1][2] += av.y * vv.z; acc[1][3] += av.y * vv.w;
            acc[2][0] += av.z * vv.x; acc[2][1] += av.z * vv.y; acc[2][2] += av.z * vv.z; acc[2][3] += av.z * vv.w;
            acc[3][0] += av.w * vv.x; acc[3][1] += av.w * vv.y; acc[3][2] += av.w * vv.z; acc[3][3] += av.w * vv.w;
        }
        #pragma unroll
        for (int a = 0; a < 4; a++) {
            int n = n0 + a;
            if (n < NN) {
                size_t o = (size_t)(m * NN + n) * CC + h * 32 + d0;
                uint32_t l0, l1;
                uint32_t h0 = split2(acc[a][0], acc[a][1], l0);
                uint32_t h1 = split2(acc[a][2], acc[a][3], l1);
                *reinterpret_cast<uint2*>(&outh[o]) = make_uint2(h0, h1);
                *reinterpret_cast<uint2*>(&outl[o]) = make_uint2(l0, l1);
            }
        }
    }
}

// ================= residuals =================
__global__ void k_resid(const float* __restrict__ x, const float* __restrict__ y,
                        float* __restrict__ out) {
    int i = blockIdx.x * blockDim.x + threadIdx.x;
    if (i >= BB * CC * HWSZ) return;
    int w = i % HH; int t = i / HH;
    int h = t % HH;  t /= HH;
    int c = t % CC;  int b = t / CC;
    int m = b * 64 + (h / WWIN) * 8 + (w / WWIN);
    int n = (h % WWIN) * WWIN + (w % WWIN);
    out[i] = x[i] + y[(size_t)(m * NN + n) * CC + c];
}
__global__ void k_resid2(float* __restrict__ out, const float* __restrict__ z) {
    int i = blockIdx.x * blockDim.x + threadIdx.x;
    if (i >= BB * CC * HWSZ) return;
    int hw = i % HWSZ;
    int c  = (i / HWSZ) % CC;
    int b  = i / (HWSZ * CC);
    out[i] += z[((size_t)b * HWSZ + hw) * CC + c];
}

// ================= host launcher =================
extern "C" void kernel_launch(void* const* d_in, const int* in_sizes, int n_in,
                              void* d_out, int out_size) {
    const float* x      = (const float*)d_in[0];
    const float* ln1_w  = (const float*)d_in[1];
    const float* ln1_b  = (const float*)d_in[2];
    const float* ln2_w  = (const float*)d_in[3];
    const float* ln2_b  = (const float*)d_in[4];
    const float* qkv_w  = (const float*)d_in[5];
    const float* qkv_b  = (const float*)d_in[6];
    const float* proj_w = (const float*)d_in[7];
    const float* proj_b = (const float*)d_in[8];
    const float* table  = (const float*)d_in[9];
    const float* fc1_w  = (const float*)d_in[10];
    const float* fc1_b  = (const float*)d_in[11];
    const float* fc2_w  = (const float*)d_in[12];
    const float* fc2_b  = (const float*)d_in[13];
    float* out = (float*)d_out;

    float *p_qkv, *p_o, *p_bias;
    __nv_bfloat16 *p_s1h, *p_s1l, *p_s2h, *p_s2l, *p_ghh, *p_ghl;
    __nv_bfloat16 *p_wqh, *p_wql, *p_wph, *p_wpl, *p_w1h, *p_w1l, *p_w2h, *p_w2l;
    cudaGetSymbolAddress((void**)&p_qkv, g_qkv);
    cudaGetSymbolAddress((void**)&p_o,   g_o);
    cudaGetSymbolAddress((void**)&p_bias,g_bias);
    cudaGetSymbolAddress((void**)&p_s1h, s1h); cudaGetSymbolAddress((void**)&p_s1l, s1l);
    cudaGetSymbolAddress((void**)&p_s2h, s2h); cudaGetSymbolAddress((void**)&p_s2l, s2l);
    cudaGetSymbolAddress((void**)&p_ghh, ghh); cudaGetSymbolAddress((void**)&p_ghl, ghl);
    cudaGetSymbolAddress((void**)&p_wqh, wqh); cudaGetSymbolAddress((void**)&p_wql, wql);
    cudaGetSymbolAddress((void**)&p_wph, wph); cudaGetSymbolAddress((void**)&p_wpl, wpl);
    cudaGetSymbolAddress((void**)&p_w1h, w1h); cudaGetSymbolAddress((void**)&p_w1l, w1l);
    cudaGetSymbolAddress((void**)&p_w2h, w2h); cudaGetSymbolAddress((void**)&p_w2l, w2l);

    cudaFuncSetAttribute(k_gemm, cudaFuncAttributeMaxDynamicSharedMemorySize, GSMEM);

    k_bias<<<(NHD * NN * NN + 255) / 256, 256>>>(table, p_bias);
    k_wsplit<<<(3 * CC * CC + 255) / 256, 256>>>(qkv_w, p_wqh, p_wql, 3 * CC * CC);
    k_wsplit<<<(CC * CC + 255) / 256, 256>>>(proj_w, p_wph, p_wpl, CC * CC);
    k_wsplit<<<(HID_ * CC + 255) / 256, 256>>>(fc1_w, p_w1h, p_w1l, HID_ * CC);
    k_wsplit<<<(CC * HID_ + 255) / 256, 256>>>(fc2_w, p_w2h, p_w2l, CC * HID_);

    k_ln<true><<<BB * HH * 2, dim3(28, 8)>>>(x, ln1_w, ln1_b, p_s1h, p_s1l);

    // attention pass 1
    k_gemm<<<dim3(NPTS / 128, 6), 256, GSMEM>>>(p_wqh, p_wql, qkv_b, p_s1h, p_s1l,
                                                p_qkv, nullptr, nullptr, CC, 3 * CC, 0);
    k_attn<<<MM * NHD, 256>>>(p_qkv, p_bias, p_s2h, p_s2l);
    k_gemm<<<dim3(NPTS / 128, 2), 256, GSMEM>>>(p_wph, p_wpl, proj_b, p_s2h, p_s2l,
                                                nullptr, p_s1h, p_s1l, CC, CC, 1);

    // attention pass 2
    k_gemm<<<dim3(NPTS / 128, 6), 256, GSMEM>>>(p_wqh, p_wql, qkv_b, p_s1h, p_s1l,
                                                p_qkv, nullptr, nullptr, CC, 3 * CC, 0);
    k_attn<<<MM * NHD, 256>>>(p_qkv, p_bias, p_s2h, p_s2l);
    k_gemm<<<dim3(NPTS / 128, 2), 256, GSMEM>>>(p_wph, p_wpl, proj_b, p_s2h, p_s2l,
                                                p_o, nullptr, nullptr, CC, CC, 0);

    // residual + unblock
    k_resid<<<(BB * CC * HWSZ + 255) / 256, 256>>>(x, p_o, out);

    // LN2 -> split (pt, C)
    k_ln<false><<<BB * HH * 2, dim3(28, 8)>>>(out, ln2_w, ln2_b, p_s1h, p_s1l);

    // MLP
    k_gemm<<<dim3(NPTS / 128, HID_ / 128), 256, GSMEM>>>(p_w1h, p_w1l, fc1_b, p_s1h, p_s1l,
                                                         nullptr, p_ghh, p_ghl, CC, HID_, 2);
    k_gemm<<<dim3(NPTS / 128, CC / 128), 256, GSMEM>>>(p_w2h, p_w2l, fc2_b, p_ghh, p_ghl,
                                                       p_o, nullptr, nullptr, HID_, CC, 0);
    k_resid2<<<(BB * CC * HWSZ + 255) / 256, 256>>>(out, p_o);
}